// round 17
// baseline (speedup 1.0000x reference)
#include <cuda_runtime.h>
#include <cuda_fp16.h>
#include <math.h>
#include <stdint.h>

#define BB 8
#define LL 512
#define DD 768
#define HH 12
#define DH 64
#define FF 3072
#define NL 6
#define NC 1
#define MM (BB*LL)   // 4096
#define NQKV 2304

typedef __half fp16;

// ---------------- scratch ----------------
__device__ float g_h[MM*DD];
__device__ fp16 g_xn[MM*DD];
__device__ fp16 g_qkv[MM*NQKV];
__device__ fp16 g_ao[MM*DD];
__device__ fp16 g_ff[MM*FF];
__device__ fp16 g_wqkv[NL*NQKV*DD];
__device__ fp16 g_wo[NL*DD*DD];
__device__ fp16 g_w1[NL*DD*FF];
__device__ fp16 g_w2[NL*FF*DD];

// ---------------- PTX helpers ----------------
__device__ __forceinline__ uint32_t smem_to_u32(const void* p) {
    uint32_t a;
    asm("{ .reg .u64 t; cvta.to.shared.u64 t, %1; cvt.u32.u64 %0, t; }" : "=r"(a) : "l"(p));
    return a;
}
__device__ __forceinline__ void cp_async16(uint32_t saddr, const void* gaddr) {
    asm volatile("cp.async.cg.shared.global [%0], [%1], 16;" :: "r"(saddr), "l"(gaddr) : "memory");
}
#define CP_COMMIT() asm volatile("cp.async.commit_group;" ::: "memory")
#define CP_WAIT1()  asm volatile("cp.async.wait_group 1;"  ::: "memory")
__device__ __forceinline__ void ldsm4(uint32_t* r, uint32_t a) {
    asm volatile("ldmatrix.sync.aligned.m8n8.x4.shared.b16 {%0,%1,%2,%3}, [%4];"
        : "=r"(r[0]), "=r"(r[1]), "=r"(r[2]), "=r"(r[3]) : "r"(a));
}
__device__ __forceinline__ void ldsm4t(uint32_t* r, uint32_t a) {
    asm volatile("ldmatrix.sync.aligned.m8n8.x4.trans.shared.b16 {%0,%1,%2,%3}, [%4];"
        : "=r"(r[0]), "=r"(r[1]), "=r"(r[2]), "=r"(r[3]) : "r"(a));
}
__device__ __forceinline__ void mma_f16(float* c, const uint32_t* a, const uint32_t* b) {
    asm volatile("mma.sync.aligned.m16n8k16.row.col.f32.f16.f16.f32 "
        "{%0,%1,%2,%3}, {%4,%5,%6,%7}, {%8,%9}, {%0,%1,%2,%3};"
        : "+f"(c[0]), "+f"(c[1]), "+f"(c[2]), "+f"(c[3])
        : "r"(a[0]), "r"(a[1]), "r"(a[2]), "r"(a[3]), "r"(b[0]), "r"(b[1]));
}
__device__ __forceinline__ uint32_t packh(fp16 a, fp16 b) {
    __half2 t; t.x = a; t.y = b; return *(uint32_t*)&t;
}

// ---------------- weight transpose -> fp16 (generic) ----------------
__global__ void tsplit_kernel(const float* __restrict__ W, fp16* __restrict__ T,
                              int K, int N, int roff, size_t out_ls) {
    __shared__ float s[32][33];
    int l = blockIdx.z;
    const float* Wl = W + (size_t)l * K * N;
    fp16* Tl = T + (size_t)l * out_ls;
    int n0 = blockIdx.x * 32, k0 = blockIdx.y * 32;
    int tx = threadIdx.x, ty = threadIdx.y;
    #pragma unroll
    for (int j = 0; j < 4; j++)
        s[ty + 8*j][tx] = Wl[(size_t)(k0 + ty + 8*j) * N + n0 + tx];
    __syncthreads();
    #pragma unroll
    for (int j = 0; j < 4; j++) {
        int row = ty + 8*j;
        Tl[(size_t)(roff + n0 + row) * K + k0 + tx] = __float2half_rn(s[tx][row]);
    }
}

// merged QKV transpose
__global__ void tsplit_qkv(const float* __restrict__ Wq, const float* __restrict__ Wk,
                           const float* __restrict__ Wv, fp16* __restrict__ T) {
    __shared__ float s[32][33];
    int z = blockIdx.z;
    int l = z / 3, which = z % 3;
    const float* W = (which == 0) ? Wq : (which == 1) ? Wk : Wv;
    const float* Wl = W + (size_t)l * DD * DD;
    fp16* Tl = T + (size_t)l * NQKV * DD;
    int roff = which * DD;
    int n0 = blockIdx.x * 32, k0 = blockIdx.y * 32;
    int tx = threadIdx.x, ty = threadIdx.y;
    #pragma unroll
    for (int j = 0; j < 4; j++)
        s[ty + 8*j][tx] = Wl[(size_t)(k0 + ty + 8*j) * DD + n0 + tx];
    __syncthreads();
    #pragma unroll
    for (int j = 0; j < 4; j++) {
        int row = ty + 8*j;
        Tl[(size_t)(roff + n0 + row) * DD + k0 + tx] = __float2half_rn(s[tx][row]);
    }
}

// ---------------- embedding + positional encoding ----------------
__global__ void embed_kernel(const int* __restrict__ x, const float* __restrict__ emb,
                             float* __restrict__ out) {
    int r = blockIdx.x;
    int b = r / LL;
    int tok = x[r];
    const float* erow = emb + (size_t)tok * DD;
    float* orow = out + (size_t)r * DD;
    const float neg_log = -logf(10000.0f) / (float)DD;
    for (int j = 0; j < 3; j++) {
        int d = threadIdx.x + j * 256;
        int i2 = (d >> 1) << 1;
        float div = expf((float)i2 * neg_log);
        float ang = (float)b * div;
        float pe = (d & 1) ? cosf(ang) : sinf(ang);
        orow[d] = erow[d] + pe;
    }
}

// ---------------- layernorm: warp-per-row -> fp16 ----------------
__global__ void ln_kernel(const float* __restrict__ in, const float* __restrict__ g,
                          const float* __restrict__ be, fp16* __restrict__ o) {
    int warp = threadIdx.x >> 5, lane = threadIdx.x & 31;
    int r = blockIdx.x * 8 + warp;
    const float* xr = in + (size_t)r * DD;
    float4 v[6];
    float s = 0.0f;
    #pragma unroll
    for (int i = 0; i < 6; i++) {
        v[i] = *(const float4*)(xr + lane*4 + i*128);
        s += v[i].x + v[i].y + v[i].z + v[i].w;
    }
    #pragma unroll
    for (int oo = 16; oo > 0; oo >>= 1) s += __shfl_xor_sync(0xFFFFFFFFu, s, oo);
    float mean = s * (1.0f / (float)DD);
    float vs = 0.0f;
    #pragma unroll
    for (int i = 0; i < 6; i++) {
        v[i].x -= mean; v[i].y -= mean; v[i].z -= mean; v[i].w -= mean;
        vs += v[i].x*v[i].x + v[i].y*v[i].y + v[i].z*v[i].z + v[i].w*v[i].w;
    }
    #pragma unroll
    for (int oo = 16; oo > 0; oo >>= 1) vs += __shfl_xor_sync(0xFFFFFFFFu, vs, oo);
    float rs = rsqrtf(vs * (1.0f / (float)DD) + 1e-5f);
    fp16* orow = o + (size_t)r * DD;
    #pragma unroll
    for (int i = 0; i < 6; i++) {
        int c = lane*4 + i*128;
        float4 gg = *(const float4*)(g + c);
        float4 bb = *(const float4*)(be + c);
        uint2 pk;
        pk.x = packh(__float2half(v[i].x * rs * gg.x + bb.x),
                     __float2half(v[i].y * rs * gg.y + bb.y));
        pk.y = packh(__float2half(v[i].z * rs * gg.z + bb.z),
                     __float2half(v[i].w * rs * gg.w + bb.w));
        *(uint2*)(orow + c) = pk;
    }
}

// ---------------- HMMA GEMM: 128x64 tile, K=64 per stage, 2-stage, 3 CTAs/SM ----------------
#define A_OFF 0
#define B_OFF 18432
#define STG_BYTES 27648
#define NSTG 2
#define GEMM_SMEM (NSTG*STG_BYTES)

__global__ __launch_bounds__(256, 3) void gemm_mma(
    const fp16* __restrict__ A, const fp16* __restrict__ B,
    const float* __restrict__ bias0, const float* __restrict__ bias1,
    const float* __restrict__ bias2,
    float* __restrict__ C, fp16* __restrict__ O,
    int Ntot, int Ktot, int op)
{
    extern __shared__ char dsmem[];
    uint32_t smem_u = smem_to_u32(dsmem);
    int tid = threadIdx.x;
    int lane = tid & 31;
    int wid = tid >> 5;
    int wm = wid & 3;
    int wn = wid >> 2;
    int bm = blockIdx.y * 128, bn = blockIdx.x * 64;

    uint32_t a_off = (uint32_t)((wm*32 + (lane & 15)) * 144 + 16 * (lane >> 4));
    uint32_t b_off = (uint32_t)((wn*32 + 8*((lane >> 4) & 1) + (lane & 7)) * 144
                                + 16 * ((lane >> 3) & 1));

    float acc[2][4][4];
    #pragma unroll
    for (int i = 0; i < 2; i++)
        #pragma unroll
        for (int j = 0; j < 4; j++)
            #pragma unroll
            for (int q = 0; q < 4; q++) acc[i][j][q] = 0.0f;

    int iters = Ktot >> 6;

    #define LOAD_STAGE(it, buf) do { \
        int k0 = (it) << 6; \
        uint32_t sb = smem_u + (buf) * STG_BYTES; \
        _Pragma("unroll") \
        for (int j = 0; j < 4; j++) { \
            int ci = tid + j * 256; \
            int row = ci >> 3, col = ci & 7; \
            cp_async16(sb + A_OFF + row*144 + col*16, A + (size_t)(bm + row) * Ktot + k0 + col*8); \
        } \
        _Pragma("unroll") \
        for (int j = 0; j < 2; j++) { \
            int ci = tid + j * 256; \
            int row = ci >> 3, col = ci & 7; \
            cp_async16(sb + B_OFF + row*144 + col*16, B + (size_t)(bn + row) * Ktot + k0 + col*8); \
        } \
    } while (0)

    LOAD_STAGE(0, 0); CP_COMMIT();
    if (iters > 1) { LOAD_STAGE(1, 1); } CP_COMMIT();

    for (int it = 0; it < iters; it++) {
        CP_WAIT1();
        __syncthreads();
        int buf = it & 1;
        uint32_t sA = smem_u + buf * STG_BYTES + A_OFF;
        uint32_t sB = smem_u + buf * STG_BYTES + B_OFF;
        #pragma unroll
        for (int ks = 0; ks < 4; ks++) {
            uint32_t a[2][4], b[2][4];
            #pragma unroll
            for (int tm = 0; tm < 2; tm++)
                ldsm4(a[tm], sA + a_off + tm*2304 + ks*32);
            #pragma unroll
            for (int p = 0; p < 2; p++)
                ldsm4(b[p], sB + b_off + p*2304 + ks*32);
            #pragma unroll
            for (int tm = 0; tm < 2; tm++)
                #pragma unroll
                for (int p = 0; p < 2; p++) {
                    mma_f16(acc[tm][2*p],   a[tm], &b[p][0]);
                    mma_f16(acc[tm][2*p+1], a[tm], &b[p][2]);
                }
        }
        __syncthreads();
        if (it + 2 < iters) LOAD_STAGE(it + 2, buf);
        CP_COMMIT();
    }
    #undef LOAD_STAGE

    const float* beff = bias0;
    int boff = 0;
    if (bias1 != nullptr) {
        if (bn >= 1536)      { beff = bias2; boff = 1536; }
        else if (bn >= 768)  { beff = bias1; boff = 768;  }
    }

    int m_base = bm + wm*32 + (lane >> 2);
    int n_base = bn + wn*32 + (lane & 3)*2;
    #pragma unroll
    for (int tm = 0; tm < 2; tm++) {
        #pragma unroll
        for (int tn = 0; tn < 4; tn++) {
            #pragma unroll
            for (int half = 0; half < 2; half++) {
                int m = m_base + tm*16 + half*8;
                int n = n_base + tn*8;
                float v0 = acc[tm][tn][2*half]     + beff[n - boff];
                float v1 = acc[tm][tn][2*half + 1] + beff[n + 1 - boff];
                size_t idx = (size_t)m * Ntot + n;
                if (op == 1) {
                    float gv0 = 0.5f * v0 * (1.0f + erff(v0 * 0.70710678118654752f));
                    float gv1 = 0.5f * v1 * (1.0f + erff(v1 * 0.70710678118654752f));
                    *(uint32_t*)(O + idx) = packh(__float2half(gv0), __float2half(gv1));
                } else if (op == 2) {
                    C[idx]     += v0;
                    C[idx + 1] += v1;
                } else {
                    *(uint32_t*)(O + idx) = packh(__float2half(v0), __float2half(v1));
                }
            }
        }
    }
}

// ---------------- persistent tensor-core attention: 32-row Q tiles, 2 CTAs/SM ----------------
// tile t -> q0 = (t % 16)*32, h = (t/16) % 12, b = t/192. Contiguous chunks per CTA
// keep (b,h) locality so K/V L2 reuse is preserved.
#define SSTR 520
#define OFF_Q  (32*SSTR*4)
#define OFF_K  (OFF_Q + 32*144)
#define ATTN_SMEM (OFF_K + 128*144)

__global__ __launch_bounds__(256, 2) void attn_tc(
    const fp16* __restrict__ QKV, const int* __restrict__ mask,
    float* __restrict__ attn_out, fp16* __restrict__ ao, int ntiles)
{
    extern __shared__ char sm[];
    float* S = (float*)sm;
    uint32_t su = smem_to_u32(sm);
    int tid = threadIdx.x, lane = tid & 31, wid = tid >> 5;

    int tstart = (int)(((long long)blockIdx.x * ntiles) / gridDim.x);
    int tend   = (int)(((long long)(blockIdx.x + 1) * ntiles) / gridDim.x);

    for (int t = tstart; t < tend; t++) {
        int q0 = (t & 15) * 32;
        int h  = (t >> 4) % 12;
        int b  = t / 192;

        // load Q tile (32 rows x 64 fp16)
        {
            int r = tid >> 3, c = tid & 7;
            size_t g = ((size_t)(b*LL + q0 + r)) * NQKV + h*DH;
            *(uint4*)(sm + OFF_Q + r*144 + c*16) = ((const uint4*)(QKV + g))[c];
        }

        for (int kc = 0; kc < 4; kc++) {
            {
                int r = tid >> 1, c0 = (tid & 1) * 4;
                size_t g = ((size_t)(b*LL + kc*128 + r)) * NQKV + 768 + h*DH;
                const uint4* gk = (const uint4*)(QKV + g);
                #pragma unroll
                for (int c = 0; c < 4; c++)
                    *(uint4*)(sm + OFF_K + r*144 + (c0+c)*16) = gk[c0+c];
            }
            __syncthreads();
            float acc[2][2][4];
            #pragma unroll
            for (int i = 0; i < 2; i++)
                #pragma unroll
                for (int j = 0; j < 2; j++)
                    #pragma unroll
                    for (int q = 0; q < 4; q++) acc[i][j][q] = 0.0f;
            uint32_t aoff = (uint32_t)((lane & 15) * 144 + 16 * (lane >> 4));
            uint32_t boff = (uint32_t)((wid*16 + 8*((lane >> 4) & 1) + (lane & 7)) * 144
                                       + 16 * ((lane >> 3) & 1));
            #pragma unroll
            for (int ki = 0; ki < 4; ki++) {
                uint32_t a[2][4], bmat[4];
                ldsm4(a[0], su + OFF_Q + aoff + ki*32);
                ldsm4(a[1], su + OFF_Q + aoff + 2304 + ki*32);
                ldsm4(bmat, su + OFF_K + boff + ki*32);
                #pragma unroll
                for (int tm = 0; tm < 2; tm++) {
                    mma_f16(acc[tm][0], a[tm], &bmat[0]);
                    mma_f16(acc[tm][1], a[tm], &bmat[2]);
                }
            }
            #pragma unroll
            for (int tm = 0; tm < 2; tm++) {
                #pragma unroll
                for (int tn = 0; tn < 2; tn++) {
                    int row = tm*16 + (lane >> 2);
                    int col = kc*128 + wid*16 + tn*8 + (lane & 3)*2;
                    int m0 = mask[b*LL + col], m1 = mask[b*LL + col + 1];
                    #pragma unroll
                    for (int half = 0; half < 2; half++) {
                        int rr = row + half*8;
                        float v0 = acc[tm][tn][2*half]   * 0.125f - 0.01f * (float)((q0 + rr) - col);
                        float v1 = acc[tm][tn][2*half+1] * 0.125f - 0.01f * (float)((q0 + rr) - (col+1));
                        if (m0 == 0) v0 = -INFINITY;
                        if (m1 == 0) v1 = -INFINITY;
                        S[rr*SSTR + col]     = v0;
                        S[rr*SSTR + col + 1] = v1;
                    }
                }
            }
            __syncthreads();
        }

        {
            size_t gbase0 = ((size_t)(b*HH + h) * LL + q0) * LL;
            #pragma unroll
            for (int j = 0; j < 4; j++) {
                int r = wid*4 + j;
                float4 e[4];
                #pragma unroll
                for (int i = 0; i < 4; i++) e[i] = *(float4*)&S[r*SSTR + i*128 + lane*4];
                float mx = -1e30f;
                #pragma unroll
                for (int i = 0; i < 4; i++)
                    mx = fmaxf(mx, fmaxf(fmaxf(e[i].x, e[i].y), fmaxf(e[i].z, e[i].w)));
                #pragma unroll
                for (int o = 16; o > 0; o >>= 1) mx = fmaxf(mx, __shfl_xor_sync(0xFFFFFFFFu, mx, o));
                float sum = 0.0f;
                #pragma unroll
                for (int i = 0; i < 4; i++) {
                    e[i].x = __expf(e[i].x - mx); e[i].y = __expf(e[i].y - mx);
                    e[i].z = __expf(e[i].z - mx); e[i].w = __expf(e[i].w - mx);
                    sum += e[i].x + e[i].y + e[i].z + e[i].w;
                }
                #pragma unroll
                for (int o = 16; o > 0; o >>= 1) sum += __shfl_xor_sync(0xFFFFFFFFu, sum, o);
                float inv = 1.0f / sum;
                float* gp = attn_out + gbase0 + (size_t)r * LL;
                #pragma unroll
                for (int i = 0; i < 4; i++) {
                    e[i].x *= inv; e[i].y *= inv; e[i].z *= inv; e[i].w *= inv;
                    *(float4*)&S[r*SSTR + i*128 + lane*4] = e[i];
                    *(float4*)(gp + i*128 + lane*4) = e[i];
                }
            }
        }
        __syncthreads();

        int wn4 = wid & 3, wk2 = wid >> 2;
        float oa[2][2][4];
        #pragma unroll
        for (int i = 0; i < 2; i++)
            #pragma unroll
            for (int j = 0; j < 2; j++)
                #pragma unroll
                for (int q = 0; q < 4; q++) oa[i][j][q] = 0.0f;

        uint32_t poff = (uint32_t)((lane & 15) * 144 + 16 * (lane >> 4));
        uint32_t voff = (uint32_t)((lane & 15) * 144 + wn4*32 + 16 * (lane >> 4));

        for (int kc = 0; kc < 8; kc++) {
            {
                int r = tid >> 3, c0 = (tid & 7) * 8;
                const float* sp = &S[r*SSTR + kc*64 + c0];
                float v[8];
                *(float4*)&v[0] = *(const float4*)sp;
                *(float4*)&v[4] = *(const float4*)(sp + 4);
                uint32_t hw[4];
                #pragma unroll
                for (int q = 0; q < 4; q++)
                    hw[q] = packh(__float2half_rn(v[2*q]), __float2half_rn(v[2*q+1]));
                *(uint4*)(sm + OFF_Q + r*144 + c0*2) = *(uint4*)hw;
            }
            {
                int r = tid >> 2, c = tid & 3;
                size_t g = ((size_t)(b*LL + kc*64 + r)) * NQKV + 1536 + h*DH;
                const uint4* gv = (const uint4*)(QKV + g);
                *(uint4*)(sm + OFF_K + r*144 + c*16)     = gv[c];
                *(uint4*)(sm + OFF_K + r*144 + (c+4)*16) = gv[c+4];
            }
            __syncthreads();
            #pragma unroll
            for (int kj = 0; kj < 2; kj++) {
                int ki = wk2*2 + kj;
                uint32_t p[2][4], v[4];
                ldsm4(p[0], su + OFF_Q + poff + ki*32);
                ldsm4(p[1], su + OFF_Q + poff + 2304 + ki*32);
                ldsm4t(v, su + OFF_K + voff + ki*2304);
                #pragma unroll
                for (int tm = 0; tm < 2; tm++) {
                    mma_f16(oa[tm][0], p[tm], &v[0]);
                    mma_f16(oa[tm][1], p[tm], &v[2]);
                }
            }
            __syncthreads();
        }

        if (wk2 == 0) {
            #pragma unroll
            for (int tm = 0; tm < 2; tm++)
                #pragma unroll
                for (int tn = 0; tn < 2; tn++)
                    #pragma unroll
                    for (int half = 0; half < 2; half++) {
                        int row = tm*16 + (lane >> 2) + half*8;
                        int col = wn4*16 + tn*8 + (lane & 3)*2;
                        S[row*64 + col]     = oa[tm][tn][2*half];
                        S[row*64 + col + 1] = oa[tm][tn][2*half+1];
                    }
        }
        __syncthreads();
        if (wk2 == 1) {
            #pragma unroll
            for (int tm = 0; tm < 2; tm++)
                #pragma unroll
                for (int tn = 0; tn < 2; tn++)
                    #pragma unroll
                    for (int half = 0; half < 2; half++) {
                        int row = tm*16 + (lane >> 2) + half*8;
                        int col = wn4*16 + tn*8 + (lane & 3)*2;
                        float v0 = oa[tm][tn][2*half]   + S[row*64 + col];
                        float v1 = oa[tm][tn][2*half+1] + S[row*64 + col + 1];
                        size_t g = ((size_t)(b*LL + q0 + row)) * DD + h*DH + col;
                        *(uint32_t*)(ao + g) = packh(__float2half(v0), __float2half(v1));
                    }
        }
        __syncthreads();   // protect S/K/Q reuse by the next tile
    }
}

// ---------------- classifier head ----------------
__global__ void logits_kernel(const float* __restrict__ h, const float* __restrict__ Wc,
                              const float* __restrict__ bc, float* __restrict__ out) {
    __shared__ float red[256];
    int b = blockIdx.x;
    int t = threadIdx.x;
    float s = 0.0f;
    for (int d = t; d < DD; d += 256) s += h[(size_t)b * LL * DD + d] * Wc[d * NC];
    red[t] = s; __syncthreads();
    for (int o = 128; o > 0; o >>= 1) { if (t < o) red[t] += red[t + o]; __syncthreads(); }
    if (t == 0) out[b * NC] = red[0] + bc[0];
}

// ---------------- launcher ----------------
extern "C" void kernel_launch(void* const* d_in, const int* in_sizes, int n_in,
                              void* d_out, int out_size) {
    const int*   x    = (const int*)  d_in[0];
    const int*   mask = (const int*)  d_in[1];
    const float* emb  = (const float*)d_in[2];
    const float* Wq   = (const float*)d_in[3];
    const float* bq   = (const float*)d_in[4];
    const float* Wk   = (const float*)d_in[5];
    const float* bk   = (const float*)d_in[6];
    const float* Wv   = (const float*)d_in[7];
    const float* bv   = (const float*)d_in[8];
    const float* Wo   = (const float*)d_in[9];
    const float* bo   = (const float*)d_in[10];
    const float* W1   = (const float*)d_in[11];
    const float* b1   = (const float*)d_in[12];
    const float* W2   = (const float*)d_in[13];
    const float* b2   = (const float*)d_in[14];
    const float* g1   = (const float*)d_in[15];
    const float* be1  = (const float*)d_in[16];
    const float* g2   = (const float*)d_in[17];
    const float* be2  = (const float*)d_in[18];
    const float* Wc   = (const float*)d_in[19];
    const float* bc   = (const float*)d_in[20];

    float* out = (float*)d_out;
    float* logits = out;
    float* attn_base = out + (size_t)BB * NC;

    static bool attr_set = false;
    if (!attr_set) {
        cudaFuncSetAttribute(gemm_mma, cudaFuncAttributeMaxDynamicSharedMemorySize, GEMM_SMEM);
        cudaFuncSetAttribute(attn_tc, cudaFuncAttributeMaxDynamicSharedMemorySize, ATTN_SMEM);
        attr_set = true;
    }

    float *p_h;
    fp16 *p_xn, *p_qkv, *p_ao, *p_ff, *p_wqkv, *p_wo, *p_w1, *p_w2;
    cudaGetSymbolAddress((void**)&p_h, g_h);
    cudaGetSymbolAddress((void**)&p_xn, g_xn);
    cudaGetSymbolAddress((void**)&p_qkv, g_qkv);
    cudaGetSymbolAddress((void**)&p_ao, g_ao);
    cudaGetSymbolAddress((void**)&p_ff, g_ff);
    cudaGetSymbolAddress((void**)&p_wqkv, g_wqkv);
    cudaGetSymbolAddress((void**)&p_wo, g_wo);
    cudaGetSymbolAddress((void**)&p_w1, g_w1);
    cudaGetSymbolAddress((void**)&p_w2, g_w2);

    dim3 tb(32, 8);
    size_t olsQKV = (size_t)NQKV * DD;

    dim3 gD(DD/64, MM/128);
    dim3 gQKV(NQKV/64, MM/128);
    dim3 gF(FF/64, MM/128);
    int ntA = (LL/32) * HH * BB;   // 1536
    int gA = ntA < 304 ? ntA : 304;

    tsplit_qkv<<<dim3(DD/32, DD/32, NL*3), tb>>>(Wq, Wk, Wv, p_wqkv);
    embed_kernel<<<MM, 256>>>(x, emb, p_h);

    for (int l = 0; l < NL; l++) {
        size_t wD = (size_t)l * DD * DD;
        size_t wF = (size_t)l * DD * FF;
        size_t wQ = (size_t)l * olsQKV;
        ln_kernel<<<MM/8, 256>>>(p_h, g1 + l*DD, be1 + l*DD, p_xn);
        gemm_mma<<<gQKV, 256, GEMM_SMEM>>>(p_xn, p_wqkv + wQ,
                                           bq + l*DD, bk + l*DD, bv + l*DD,
                                           nullptr, p_qkv, NQKV, DD, 3);
        if (l == 0) {
            tsplit_kernel<<<dim3(DD/32, DD/32, NL), tb>>>(Wo, p_wo, DD, DD, 0, (size_t)DD*DD);
            tsplit_kernel<<<dim3(FF/32, DD/32, NL), tb>>>(W1, p_w1, DD, FF, 0, (size_t)DD*FF);
            tsplit_kernel<<<dim3(DD/32, FF/32, NL), tb>>>(W2, p_w2, FF, DD, 0, (size_t)FF*DD);
        }
        attn_tc<<<gA, 256, ATTN_SMEM>>>(p_qkv, mask,
                                        attn_base + (size_t)l * BB * HH * LL * LL, p_ao, ntA);
        gemm_mma<<<gD, 256, GEMM_SMEM>>>(p_ao, p_wo + wD,
                                         bo + l*DD, nullptr, nullptr,
                                         p_h, nullptr, DD, DD, 2);
        ln_kernel<<<MM/8, 256>>>(p_h, g2 + l*DD, be2 + l*DD, p_xn);
        gemm_mma<<<gF, 256, GEMM_SMEM>>>(p_xn, p_w1 + wF,
                                         b1 + l*FF, nullptr, nullptr,
                                         nullptr, p_ff, FF, DD, 1);
        gemm_mma<<<gD, 256, GEMM_SMEM>>>(p_ff, p_w2 + wF,
                                         b2 + l*DD, nullptr, nullptr,
                                         p_h, nullptr, DD, FF, 2);
    }

    logits_kernel<<<BB, 256>>>(p_h, Wc, bc, logits);
}